// round 1
// baseline (speedup 1.0000x reference)
#include <cuda_runtime.h>
#include <cstdint>

// ---------------------------------------------------------------------------
// HouseholderFlow: z <- chain of 8 Householder reflections, v-chain via GEMMs.
//   v0 = h_last @ W0^T + b0 ; z = HF(v0, z)
//   v_{j+1} = v_j @ Ws[j]^T + bs[j] ; z = HF(v_{j+1}, z)
// GEMM: NT layout (A [M,K] row-major, W [N,K] row-major), fp32, packed f32x2
// FMA inner loop (FFMA2) for 2x fp32 rate on sm_103a.
// ---------------------------------------------------------------------------

#define BM 128
#define BN 128
#define BK 8
#define GEMM_THREADS 256

static const size_t MAX_ELEMS = (size_t)8192 * 2048;
__device__ float g_v0[MAX_ELEMS];
__device__ float g_v1[MAX_ELEMS];

__device__ __forceinline__ unsigned long long pack2(float x) {
    unsigned long long r;
    asm("mov.b64 %0, {%1, %1};" : "=l"(r) : "f"(x));
    return r;
}

__device__ __forceinline__ void ffma2(unsigned long long& d,
                                      unsigned long long a,
                                      unsigned long long b) {
    asm("fma.rn.f32x2 %0, %1, %2, %0;" : "+l"(d) : "l"(a), "l"(b));
}

__device__ __forceinline__ float2 unpack2(unsigned long long v) {
    float2 f;
    asm("mov.b64 {%0, %1}, %2;" : "=f"(f.x), "=f"(f.y) : "l"(v));
    return f;
}

// C[m,n] = sum_k A[m,k] * W[n,k] + bias[n]
// A: [M,K] row-major, W: [N,K] row-major, C: [M,N] row-major.
// Requires M % 128 == 0, N % 128 == 0, K % 8 == 0, 16B-aligned pointers.
__global__ __launch_bounds__(GEMM_THREADS, 2)
void gemm_nt_f32x2(const float* __restrict__ A,
                   const float* __restrict__ W,
                   const float* __restrict__ bias,
                   float* __restrict__ C,
                   int M, int N, int K) {
    __shared__ __align__(16) float As[BK][BM];
    __shared__ __align__(16) float Bs[BK][BN];

    const int tid = threadIdx.x;
    const int bm = blockIdx.y * BM;
    const int bn = blockIdx.x * BN;

    // global->smem loader mapping: one float4 per thread per tile
    const int lrow = tid >> 1;          // 0..127
    const int lk   = (tid & 1) << 2;    // 0 or 4

    const float* Ag = A + (size_t)(bm + lrow) * K + lk;
    const float* Wg = W + (size_t)(bn + lrow) * K + lk;

    // compute mapping: 16x16 thread grid, 8x8 outputs per thread
    const int tx = tid & 15;
    const int ty = tid >> 4;
    const int ty8 = ty << 3;
    const int tx8 = tx << 3;

    // accumulators: 8 rows x 4 packed (f32x2) cols = 64 fp32 values
    unsigned long long c2[8][4];
#pragma unroll
    for (int i = 0; i < 8; ++i)
#pragma unroll
        for (int j = 0; j < 4; ++j) c2[i][j] = 0ull;

    float4 aReg = *reinterpret_cast<const float4*>(Ag);
    float4 wReg = *reinterpret_cast<const float4*>(Wg);

    for (int k0 = 0; k0 < K; k0 += BK) {
        As[lk + 0][lrow] = aReg.x;
        As[lk + 1][lrow] = aReg.y;
        As[lk + 2][lrow] = aReg.z;
        As[lk + 3][lrow] = aReg.w;
        Bs[lk + 0][lrow] = wReg.x;
        Bs[lk + 1][lrow] = wReg.y;
        Bs[lk + 2][lrow] = wReg.z;
        Bs[lk + 3][lrow] = wReg.w;
        __syncthreads();

        if (k0 + BK < K) {
            aReg = *reinterpret_cast<const float4*>(Ag + k0 + BK);
            wReg = *reinterpret_cast<const float4*>(Wg + k0 + BK);
        }

#pragma unroll
        for (int k = 0; k < BK; ++k) {
            const float4 a0 = *reinterpret_cast<const float4*>(&As[k][ty8]);
            const float4 a1 = *reinterpret_cast<const float4*>(&As[k][ty8 + 4]);
            const ulonglong2 bp0 = *reinterpret_cast<const ulonglong2*>(&Bs[k][tx8]);
            const ulonglong2 bp1 = *reinterpret_cast<const ulonglong2*>(&Bs[k][tx8 + 4]);

            unsigned long long av[8];
            av[0] = pack2(a0.x); av[1] = pack2(a0.y);
            av[2] = pack2(a0.z); av[3] = pack2(a0.w);
            av[4] = pack2(a1.x); av[5] = pack2(a1.y);
            av[6] = pack2(a1.z); av[7] = pack2(a1.w);
            unsigned long long bv[4] = {bp0.x, bp0.y, bp1.x, bp1.y};

#pragma unroll
            for (int i = 0; i < 8; ++i) {
#pragma unroll
                for (int j = 0; j < 4; ++j) ffma2(c2[i][j], av[i], bv[j]);
            }
        }
        __syncthreads();
    }

    // epilogue: unpack, add bias, store
    const int ccol = bn + tx8;
    const float4 bias0 = *reinterpret_cast<const float4*>(&bias[ccol]);
    const float4 bias1 = *reinterpret_cast<const float4*>(&bias[ccol + 4]);

#pragma unroll
    for (int i = 0; i < 8; ++i) {
        const float2 p0 = unpack2(c2[i][0]);
        const float2 p1 = unpack2(c2[i][1]);
        const float2 p2 = unpack2(c2[i][2]);
        const float2 p3 = unpack2(c2[i][3]);
        float4 o0 = make_float4(p0.x + bias0.x, p0.y + bias0.y,
                                p1.x + bias0.z, p1.y + bias0.w);
        float4 o1 = make_float4(p2.x + bias1.x, p2.y + bias1.y,
                                p3.x + bias1.z, p3.y + bias1.w);
        float* cp = C + (size_t)(bm + ty8 + i) * N + ccol;
        *reinterpret_cast<float4*>(cp)     = o0;
        *reinterpret_cast<float4*>(cp + 4) = o1;
    }
}

// One block per batch row: z_new = z - 2 v (v.z)/(v.v). Zin may alias Zout.
// Supports L <= 4096, L % 1024 == 0.
__global__ __launch_bounds__(256)
void hflow_kernel(const float* __restrict__ V,
                  const float* __restrict__ Zin,
                  float* __restrict__ Zout, int L) {
    const size_t base = (size_t)blockIdx.x * L;
    const float4* v4 = reinterpret_cast<const float4*>(V + base);
    const float4* z4 = reinterpret_cast<const float4*>(Zin + base);
    float4* o4 = reinterpret_cast<float4*>(Zout + base);
    const int n4 = L >> 2;

    float4 vr[4], zr[4];
    float vz = 0.f, vv = 0.f;
    int cnt = 0;
    for (int idx = threadIdx.x; idx < n4; idx += 256) {
        const float4 v = v4[idx];
        const float4 z = z4[idx];
        vr[cnt] = v; zr[cnt] = z; ++cnt;
        vz += v.x * z.x + v.y * z.y + v.z * z.z + v.w * z.w;
        vv += v.x * v.x + v.y * v.y + v.z * v.z + v.w * v.w;
    }

#pragma unroll
    for (int off = 16; off > 0; off >>= 1) {
        vz += __shfl_xor_sync(0xffffffffu, vz, off);
        vv += __shfl_xor_sync(0xffffffffu, vv, off);
    }
    __shared__ float svz[8], svv[8];
    const int w = threadIdx.x >> 5;
    if ((threadIdx.x & 31) == 0) { svz[w] = vz; svv[w] = vv; }
    __syncthreads();
    float tvz = 0.f, tvv = 0.f;
#pragma unroll
    for (int i = 0; i < 8; ++i) { tvz += svz[i]; tvv += svv[i]; }

    const float s = -2.0f * tvz / tvv;

    cnt = 0;
    for (int idx = threadIdx.x; idx < n4; idx += 256) {
        const float4 v = vr[cnt];
        const float4 z = zr[cnt]; ++cnt;
        o4[idx] = make_float4(z.x + s * v.x, z.y + s * v.y,
                              z.z + s * v.z, z.w + s * v.w);
    }
}

extern "C" void kernel_launch(void* const* d_in, const int* in_sizes, int n_in,
                              void* d_out, int out_size) {
    const float* z      = (const float*)d_in[0];  // [B, L]
    const float* h_last = (const float*)d_in[1];  // [B, H]
    const float* W0     = (const float*)d_in[2];  // [L, H]
    const float* b0     = (const float*)d_in[3];  // [L]
    const float* Ws     = (const float*)d_in[4];  // [NF-1, L, L]
    const float* bs     = (const float*)d_in[5];  // [NF-1, L]

    const int L = in_sizes[3];
    const int B = in_sizes[0] / L;
    const int H = in_sizes[2] / L;
    const int nsteps = in_sizes[5] / L;  // NF - 1

    float* zout = (float*)d_out;

    void* p0 = nullptr;
    void* p1 = nullptr;
    cudaGetSymbolAddress(&p0, g_v0);
    cudaGetSymbolAddress(&p1, g_v1);
    float* vbuf[2] = {(float*)p0, (float*)p1};

    const dim3 gblock(GEMM_THREADS);
    const dim3 ggrid(L / BN, B / BM);

    // v0 = h_last @ W0^T + b0
    gemm_nt_f32x2<<<ggrid, gblock>>>(h_last, W0, b0, vbuf[0], B, L, H);
    // z = HF(v0, z_in) -> zout
    hflow_kernel<<<B, 256>>>(vbuf[0], z, zout, L);

    int cur = 0;
    for (int j = 0; j < nsteps; ++j) {
        const int nxt = cur ^ 1;
        gemm_nt_f32x2<<<ggrid, gblock>>>(vbuf[cur], Ws + (size_t)j * L * L,
                                         bs + (size_t)j * L, vbuf[nxt], B, L, L);
        hflow_kernel<<<B, 256>>>(vbuf[nxt], zout, zout, L);
        cur = nxt;
    }
}

// round 3
// speedup vs baseline: 3.0109x; 3.0109x over previous
#include <cuda_runtime.h>
#include <cuda_bf16.h>
#include <cstdint>

// ---------------------------------------------------------------------------
// HouseholderFlow via warp-level mma.sync (HMMA, base sm_103 ISA) bf16x3 GEMM.
//   v_{j+1} = v_j @ W^T + b  as  C = Ahi*Bhi^T + Ahi*Blo^T + Alo*Bhi^T (fp32 acc)
//   z <- z - 2 v (v.z)/||v||^2 per row.
// tcgen05 is NOT available: harness compiles PTX at target sm_103 (no 'a').
// ---------------------------------------------------------------------------

#define BM 128
#define BN 128
#define BK 64
#define NTHREADS 256
#define NSTAGES 3

#define OFF_A0 0
#define OFF_A1 16384
#define OFF_B0 32768
#define OFF_B1 49152
#define STAGE_BYTES 65536
#define SMEM_TOTAL (NSTAGES * STAGE_BYTES)

#define MAXB 8192
#define MAXL 2048
#define MAXNF 8

__device__ __nv_bfloat16 g_w_hi[(size_t)MAXNF * MAXL * MAXL];
__device__ __nv_bfloat16 g_w_lo[(size_t)MAXNF * MAXL * MAXL];
__device__ __nv_bfloat16 g_a_hi[2][(size_t)MAXB * MAXL];
__device__ __nv_bfloat16 g_a_lo[2][(size_t)MAXB * MAXL];
__device__ float g_v[(size_t)MAXB * MAXL];

// ---------------- PTX helpers (base ISA only) ----------------

__device__ __forceinline__ uint32_t smem_u32(const void* p) {
    uint32_t a;
    asm("{ .reg .u64 t; cvta.to.shared.u64 t, %1; cvt.u32.u64 %0, t; }"
        : "=r"(a) : "l"(p));
    return a;
}

__device__ __forceinline__ void cp_async_16(uint32_t saddr, const void* gaddr) {
    asm volatile("cp.async.cg.shared.global [%0], [%1], 16;" :: "r"(saddr), "l"(gaddr));
}
#define CP_COMMIT() asm volatile("cp.async.commit_group;" ::: "memory")
#define CP_WAIT(n)  asm volatile("cp.async.wait_group %0;" :: "n"(n) : "memory")

__device__ __forceinline__ void ldsm_x4(uint32_t* r, uint32_t addr) {
    asm volatile("ldmatrix.sync.aligned.m8n8.x4.shared.b16 {%0,%1,%2,%3}, [%4];"
                 : "=r"(r[0]), "=r"(r[1]), "=r"(r[2]), "=r"(r[3]) : "r"(addr));
}

__device__ __forceinline__ void mma_bf16(float* d, const uint32_t* a, const uint32_t* b) {
    asm volatile(
        "mma.sync.aligned.m16n8k16.row.col.f32.bf16.bf16.f32 "
        "{%0,%1,%2,%3}, {%4,%5,%6,%7}, {%8,%9}, {%0,%1,%2,%3};"
        : "+f"(d[0]), "+f"(d[1]), "+f"(d[2]), "+f"(d[3])
        : "r"(a[0]), "r"(a[1]), "r"(a[2]), "r"(a[3]), "r"(b[0]), "r"(b[1]));
}

// ---------------- GEMM kernel ----------------
// C[m,n] = sum_k A[m,k]*W[n,k] + bias[n]. A:[M,K], W:[N,K], both bf16 hi/lo.
// Writes C as fp32 (Vout) and bf16 hi/lo (OutHi/OutLo) for the next GEMM.
__global__ __launch_bounds__(NTHREADS, 1)
void mma_bf16x3_kernel(const __nv_bfloat16* __restrict__ Ahi,
                       const __nv_bfloat16* __restrict__ Alo,
                       const __nv_bfloat16* __restrict__ Whi,
                       const __nv_bfloat16* __restrict__ Wlo,
                       const float* __restrict__ bias,
                       float* __restrict__ Vout,
                       __nv_bfloat16* __restrict__ OutHi,
                       __nv_bfloat16* __restrict__ OutLo,
                       int M, int N, int K) {
    extern __shared__ __align__(1024) char smem_raw[];
    const uint32_t sb = smem_u32(smem_raw);

    const int tid = threadIdx.x;
    const int lane = tid & 31;
    const int wid = tid >> 5;
    const int wm = wid & 3;   // 4 warps along M: 4*32 = 128
    const int wn = wid >> 2;  // 2 warps along N: 2*64 = 128
    const int bm = blockIdx.y * BM;
    const int bn = blockIdx.x * BN;

    // ---- cp.async stage loader: 128 rows x 64 bf16 (128B) per tile, XOR swizzle ----
    auto load_stage = [&](int k0, int s) {
        const uint32_t st = sb + (uint32_t)s * STAGE_BYTES;
#pragma unroll
        for (int it = 0; it < 4; ++it) {
            int q = tid + it * NTHREADS;              // 0..1023
            int row = q >> 3, kc = q & 7;
            uint32_t so = (uint32_t)(row * 128 + ((kc ^ (row & 7)) << 4));
            size_t gea = (size_t)(bm + row) * K + k0 + kc * 8;
            size_t geb = (size_t)(bn + row) * K + k0 + kc * 8;
            cp_async_16(st + OFF_A0 + so, Ahi + gea);
            cp_async_16(st + OFF_A1 + so, Alo + gea);
            cp_async_16(st + OFF_B0 + so, Whi + geb);
            cp_async_16(st + OFF_B1 + so, Wlo + geb);
        }
    };

    // ---- per-lane ldmatrix address components ----
    // A (x4 -> a0..a3 of m16k16): lane row = m0 + (lane&15), chunk = 2k + (lane>>4)
    int aRow[2], bRow[4];
#pragma unroll
    for (int mi = 0; mi < 2; ++mi) aRow[mi] = wm * 32 + mi * 16 + (lane & 15);
    // B (x4 -> two n8 frags of k16): lane row = n0 + ((lane>>4)<<3) + (lane&7),
    //                                chunk = 2k + ((lane>>3)&1)
#pragma unroll
    for (int ni = 0; ni < 4; ++ni)
        bRow[ni] = wn * 64 + ni * 16 + ((lane >> 4) << 3) + (lane & 7);
    const int aCh = lane >> 4;
    const int bCh = (lane >> 3) & 1;

    float acc[2][8][4];
#pragma unroll
    for (int mi = 0; mi < 2; ++mi)
#pragma unroll
        for (int ni = 0; ni < 8; ++ni)
#pragma unroll
            for (int r = 0; r < 4; ++r) acc[mi][ni][r] = 0.f;

    const int NS = K / BK;
    load_stage(0, 0);      CP_COMMIT();
    load_stage(BK, 1);     CP_COMMIT();
    load_stage(2 * BK, 2); CP_COMMIT();

    for (int i = 0; i < NS; ++i) {
        const int s = i % NSTAGES;
        const uint32_t st = sb + (uint32_t)s * STAGE_BYTES;
        CP_WAIT(2);
        __syncthreads();

#pragma unroll
        for (int k = 0; k < 4; ++k) {                 // 4 x k16 within BK=64
            uint32_t ah[2][4], al[2][4], bh[4][4], bl[4][4];
#pragma unroll
            for (int mi = 0; mi < 2; ++mi) {
                uint32_t off = (uint32_t)(aRow[mi] * 128 +
                                (((2 * k + aCh) ^ (aRow[mi] & 7)) << 4));
                ldsm_x4(ah[mi], st + OFF_A0 + off);
                ldsm_x4(al[mi], st + OFF_A1 + off);
            }
#pragma unroll
            for (int ni = 0; ni < 4; ++ni) {
                uint32_t off = (uint32_t)(bRow[ni] * 128 +
                                (((2 * k + bCh) ^ (bRow[ni] & 7)) << 4));
                ldsm_x4(bh[ni], st + OFF_B0 + off);
                ldsm_x4(bl[ni], st + OFF_B1 + off);
            }
#pragma unroll
            for (int mi = 0; mi < 2; ++mi) {
#pragma unroll
                for (int ni = 0; ni < 8; ++ni) {
                    const int g = ni >> 1, h = (ni & 1) * 2;
                    mma_bf16(acc[mi][ni], ah[mi], &bh[g][h]);  // hi*hi
                    mma_bf16(acc[mi][ni], ah[mi], &bl[g][h]);  // hi*lo
                    mma_bf16(acc[mi][ni], al[mi], &bh[g][h]);  // lo*hi
                }
            }
        }

        __syncthreads();
        if (i + NSTAGES < NS) load_stage((i + NSTAGES) * BK, s);
        CP_COMMIT();
    }

    // ---- epilogue: bias add, write fp32 + bf16 hi/lo ----
    const int quad = lane >> 2;
    const int tc = (lane & 3) * 2;
#pragma unroll
    for (int mi = 0; mi < 2; ++mi) {
#pragma unroll
        for (int ni = 0; ni < 8; ++ni) {
            const int col = bn + wn * 64 + ni * 8 + tc;
            const int r0 = bm + wm * 32 + mi * 16 + quad;
            const float2 b2 = *reinterpret_cast<const float2*>(bias + col);
            float2 o0, o1;
            o0.x = acc[mi][ni][0] + b2.x; o0.y = acc[mi][ni][1] + b2.y;
            o1.x = acc[mi][ni][2] + b2.x; o1.y = acc[mi][ni][3] + b2.y;
            *reinterpret_cast<float2*>(Vout + (size_t)r0 * N + col) = o0;
            *reinterpret_cast<float2*>(Vout + (size_t)(r0 + 8) * N + col) = o1;

            __nv_bfloat162 h0, h1, l0, l1;
            h0.x = __float2bfloat16(o0.x); h0.y = __float2bfloat16(o0.y);
            h1.x = __float2bfloat16(o1.x); h1.y = __float2bfloat16(o1.y);
            l0.x = __float2bfloat16(o0.x - __bfloat162float(h0.x));
            l0.y = __float2bfloat16(o0.y - __bfloat162float(h0.y));
            l1.x = __float2bfloat16(o1.x - __bfloat162float(h1.x));
            l1.y = __float2bfloat16(o1.y - __bfloat162float(h1.y));
            *reinterpret_cast<__nv_bfloat162*>(OutHi + (size_t)r0 * N + col) = h0;
            *reinterpret_cast<__nv_bfloat162*>(OutHi + (size_t)(r0 + 8) * N + col) = h1;
            *reinterpret_cast<__nv_bfloat162*>(OutLo + (size_t)r0 * N + col) = l0;
            *reinterpret_cast<__nv_bfloat162*>(OutLo + (size_t)(r0 + 8) * N + col) = l1;
        }
    }
}

// ---------------- fp32 -> bf16 hi/lo split ----------------
__global__ __launch_bounds__(256)
void split_bf16_kernel(const float* __restrict__ src,
                       __nv_bfloat16* __restrict__ hi,
                       __nv_bfloat16* __restrict__ lo,
                       size_t n) {
    size_t i = ((size_t)blockIdx.x * 256 + threadIdx.x) * 4;
    if (i >= n) return;
    float4 x = *reinterpret_cast<const float4*>(src + i);
    __nv_bfloat162 hh0, hh1, ll0, ll1;
    hh0.x = __float2bfloat16(x.x); hh0.y = __float2bfloat16(x.y);
    hh1.x = __float2bfloat16(x.z); hh1.y = __float2bfloat16(x.w);
    ll0.x = __float2bfloat16(x.x - __bfloat162float(hh0.x));
    ll0.y = __float2bfloat16(x.y - __bfloat162float(hh0.y));
    ll1.x = __float2bfloat16(x.z - __bfloat162float(hh1.x));
    ll1.y = __float2bfloat16(x.w - __bfloat162float(hh1.y));
    *reinterpret_cast<__nv_bfloat162*>(hi + i) = hh0;
    *reinterpret_cast<__nv_bfloat162*>(hi + i + 2) = hh1;
    *reinterpret_cast<__nv_bfloat162*>(lo + i) = ll0;
    *reinterpret_cast<__nv_bfloat162*>(lo + i + 2) = ll1;
}

// ---------------- Householder reflection ----------------
__global__ __launch_bounds__(256)
void hflow_kernel(const float* __restrict__ V,
                  const float* __restrict__ Zin,
                  float* __restrict__ Zout, int L) {
    const size_t base = (size_t)blockIdx.x * L;
    const float4* v4 = reinterpret_cast<const float4*>(V + base);
    const float4* z4 = reinterpret_cast<const float4*>(Zin + base);
    float4* o4 = reinterpret_cast<float4*>(Zout + base);
    const int n4 = L >> 2;

    float4 vr[4], zr[4];
    float vz = 0.f, vv = 0.f;
    int cnt = 0;
    for (int idx = threadIdx.x; idx < n4; idx += 256) {
        const float4 v = v4[idx];
        const float4 z = z4[idx];
        vr[cnt] = v; zr[cnt] = z; ++cnt;
        vz += v.x * z.x + v.y * z.y + v.z * z.z + v.w * z.w;
        vv += v.x * v.x + v.y * v.y + v.z * v.z + v.w * v.w;
    }
#pragma unroll
    for (int off = 16; off > 0; off >>= 1) {
        vz += __shfl_xor_sync(0xffffffffu, vz, off);
        vv += __shfl_xor_sync(0xffffffffu, vv, off);
    }
    __shared__ float svz[8], svv[8];
    const int w = threadIdx.x >> 5;
    if ((threadIdx.x & 31) == 0) { svz[w] = vz; svv[w] = vv; }
    __syncthreads();
    float tvz = 0.f, tvv = 0.f;
#pragma unroll
    for (int i = 0; i < 8; ++i) { tvz += svz[i]; tvv += svv[i]; }
    const float s = -2.0f * tvz / tvv;

    cnt = 0;
    for (int idx = threadIdx.x; idx < n4; idx += 256) {
        const float4 v = vr[cnt];
        const float4 z = zr[cnt]; ++cnt;
        o4[idx] = make_float4(z.x + s * v.x, z.y + s * v.y,
                              z.z + s * v.z, z.w + s * v.w);
    }
}

// ---------------- host launcher ----------------
extern "C" void kernel_launch(void* const* d_in, const int* in_sizes, int n_in,
                              void* d_out, int out_size) {
    const float* z      = (const float*)d_in[0];  // [B, L]
    const float* h_last = (const float*)d_in[1];  // [B, H]
    const float* W0     = (const float*)d_in[2];  // [L, H]
    const float* b0     = (const float*)d_in[3];  // [L]
    const float* Ws     = (const float*)d_in[4];  // [NF-1, L, L]
    const float* bs     = (const float*)d_in[5];  // [NF-1, L]

    const int L = in_sizes[3];
    const int B = in_sizes[0] / L;
    const int H = in_sizes[2] / L;
    const int nsteps = in_sizes[5] / L;  // NF - 1

    float* zout = (float*)d_out;

    void *pwh, *pwl, *pah, *pal, *pv;
    cudaGetSymbolAddress(&pwh, g_w_hi);
    cudaGetSymbolAddress(&pwl, g_w_lo);
    cudaGetSymbolAddress(&pah, g_a_hi);
    cudaGetSymbolAddress(&pal, g_a_lo);
    cudaGetSymbolAddress(&pv, g_v);
    __nv_bfloat16* whi = (__nv_bfloat16*)pwh;
    __nv_bfloat16* wlo = (__nv_bfloat16*)pwl;
    __nv_bfloat16* ahi[2] = {(__nv_bfloat16*)pah, (__nv_bfloat16*)pah + (size_t)MAXB * MAXL};
    __nv_bfloat16* alo[2] = {(__nv_bfloat16*)pal, (__nv_bfloat16*)pal + (size_t)MAXB * MAXL};
    float* v = (float*)pv;

    cudaFuncSetAttribute(mma_bf16x3_kernel,
                         cudaFuncAttributeMaxDynamicSharedMemorySize, SMEM_TOTAL);

    // weight + input splits
    {
        size_t n0 = (size_t)L * H;
        split_bf16_kernel<<<(unsigned)(n0 / 4 / 256), 256>>>(W0, whi, wlo, n0);
        size_t nw = (size_t)nsteps * L * L;
        split_bf16_kernel<<<(unsigned)(nw / 4 / 256), 256>>>(Ws, whi + n0, wlo + n0, nw);
        size_t na = (size_t)B * H;
        split_bf16_kernel<<<(unsigned)(na / 4 / 256), 256>>>(h_last, ahi[0], alo[0], na);
    }

    const dim3 gblock(NTHREADS);
    const dim3 ggrid(L / BN, B / BM);

    int cur = 0;
    for (int j = 0; j <= nsteps; ++j) {
        const int K = (j == 0) ? H : L;
        const __nv_bfloat16* wh = whi + ((j == 0) ? 0 : (size_t)L * H + (size_t)(j - 1) * L * L);
        const __nv_bfloat16* wl = wlo + ((j == 0) ? 0 : (size_t)L * H + (size_t)(j - 1) * L * L);
        const float* bias = (j == 0) ? b0 : bs + (size_t)(j - 1) * L;
        const int nxt = cur ^ 1;

        mma_bf16x3_kernel<<<ggrid, gblock, SMEM_TOTAL>>>(
            ahi[cur], alo[cur], wh, wl, bias, v, ahi[nxt], alo[nxt], B, L, K);
        hflow_kernel<<<B, 256>>>(v, (j == 0) ? z : zout, zout, L);
        cur = nxt;
    }
}

// round 4
// speedup vs baseline: 3.1244x; 1.0377x over previous
#include <cuda_runtime.h>
#include <cuda_bf16.h>
#include <cstdint>

// ---------------------------------------------------------------------------
// HouseholderFlow via warp-level mma.sync (HMMA, base sm_103 ISA) bf16x3 GEMM.
//   v_{j+1} = v_j @ W^T + b  as  C = Ahi*Bhi^T + Ahi*Blo^T + Alo*Bhi^T (fp32 acc)
//   z <- z - 2 v (v.z)/||v||^2 per row.
// R4: CTA tile 128x64, 2 CTAs/SM (96KB smem, <=128 regs), pass-major MMA
// ordering, double-buffered ldmatrix fragments.
// ---------------------------------------------------------------------------

#define BM 128
#define BN 64
#define BK 64
#define NTHREADS 256
#define NSTAGES 2

#define OFF_A0 0
#define OFF_A1 16384
#define OFF_B0 32768
#define OFF_B1 40960
#define STAGE_BYTES 49152
#define SMEM_TOTAL (NSTAGES * STAGE_BYTES)

#define MAXB 8192
#define MAXL 2048
#define MAXNF 8

__device__ __nv_bfloat16 g_w_hi[(size_t)MAXNF * MAXL * MAXL];
__device__ __nv_bfloat16 g_w_lo[(size_t)MAXNF * MAXL * MAXL];
__device__ __nv_bfloat16 g_a_hi[2][(size_t)MAXB * MAXL];
__device__ __nv_bfloat16 g_a_lo[2][(size_t)MAXB * MAXL];
__device__ float g_v[(size_t)MAXB * MAXL];

// ---------------- PTX helpers (base ISA only) ----------------

__device__ __forceinline__ uint32_t smem_u32(const void* p) {
    uint32_t a;
    asm("{ .reg .u64 t; cvta.to.shared.u64 t, %1; cvt.u32.u64 %0, t; }"
        : "=r"(a) : "l"(p));
    return a;
}

__device__ __forceinline__ void cp_async_16(uint32_t saddr, const void* gaddr) {
    asm volatile("cp.async.cg.shared.global [%0], [%1], 16;" :: "r"(saddr), "l"(gaddr));
}
#define CP_COMMIT() asm volatile("cp.async.commit_group;" ::: "memory")
#define CP_WAIT(n)  asm volatile("cp.async.wait_group %0;" :: "n"(n) : "memory")

__device__ __forceinline__ void ldsm_x4(uint32_t* r, uint32_t addr) {
    asm volatile("ldmatrix.sync.aligned.m8n8.x4.shared.b16 {%0,%1,%2,%3}, [%4];"
                 : "=r"(r[0]), "=r"(r[1]), "=r"(r[2]), "=r"(r[3]) : "r"(addr));
}

__device__ __forceinline__ void mma_bf16(float* d, const uint32_t* a, const uint32_t* b) {
    asm volatile(
        "mma.sync.aligned.m16n8k16.row.col.f32.bf16.bf16.f32 "
        "{%0,%1,%2,%3}, {%4,%5,%6,%7}, {%8,%9}, {%0,%1,%2,%3};"
        : "+f"(d[0]), "+f"(d[1]), "+f"(d[2]), "+f"(d[3])
        : "r"(a[0]), "r"(a[1]), "r"(a[2]), "r"(a[3]), "r"(b[0]), "r"(b[1]));
}

// ---------------- GEMM kernel ----------------
// C[m,n] = sum_k A[m,k]*W[n,k] + bias[n]. A:[M,K], W:[N,K], both bf16 hi/lo.
// Writes C as fp32 (Vout) and bf16 hi/lo (OutHi/OutLo) for the next GEMM.
__global__ __launch_bounds__(NTHREADS, 2)
void mma_bf16x3_kernel(const __nv_bfloat16* __restrict__ Ahi,
                       const __nv_bfloat16* __restrict__ Alo,
                       const __nv_bfloat16* __restrict__ Whi,
                       const __nv_bfloat16* __restrict__ Wlo,
                       const float* __restrict__ bias,
                       float* __restrict__ Vout,
                       __nv_bfloat16* __restrict__ OutHi,
                       __nv_bfloat16* __restrict__ OutLo,
                       int M, int N, int K) {
    extern __shared__ __align__(1024) char smem_raw[];
    const uint32_t sb = smem_u32(smem_raw);

    const int tid = threadIdx.x;
    const int lane = tid & 31;
    const int wid = tid >> 5;
    const int wm = wid & 3;   // 4 warps along M: 4*32 = 128
    const int wn = wid >> 2;  // 2 warps along N: 2*32 = 64
    const int bm = blockIdx.y * BM;
    const int bn = blockIdx.x * BN;

    // ---- cp.async stage loader: rows x 64 bf16 (128B) per tile, XOR swizzle ----
    auto load_stage = [&](int k0, int s) {
        const uint32_t st = sb + (uint32_t)s * STAGE_BYTES;
#pragma unroll
        for (int it = 0; it < 4; ++it) {              // A: 128 rows * 8 chunks
            int q = tid + it * NTHREADS;
            int row = q >> 3, kc = q & 7;
            uint32_t so = (uint32_t)(row * 128 + ((kc ^ (row & 7)) << 4));
            size_t ge = (size_t)(bm + row) * K + k0 + kc * 8;
            cp_async_16(st + OFF_A0 + so, Ahi + ge);
            cp_async_16(st + OFF_A1 + so, Alo + ge);
        }
#pragma unroll
        for (int it = 0; it < 2; ++it) {              // B: 64 rows * 8 chunks
            int q = tid + it * NTHREADS;
            int row = q >> 3, kc = q & 7;
            uint32_t so = (uint32_t)(row * 128 + ((kc ^ (row & 7)) << 4));
            size_t ge = (size_t)(bn + row) * K + k0 + kc * 8;
            cp_async_16(st + OFF_B0 + so, Whi + ge);
            cp_async_16(st + OFF_B1 + so, Wlo + ge);
        }
    };

    // ---- per-lane ldmatrix address components ----
    int aRow[2], bRow[2];
#pragma unroll
    for (int mi = 0; mi < 2; ++mi) aRow[mi] = wm * 32 + mi * 16 + (lane & 15);
#pragma unroll
    for (int g = 0; g < 2; ++g)
        bRow[g] = wn * 32 + g * 16 + ((lane >> 4) << 3) + (lane & 7);
    const int aCh = lane >> 4;
    const int bCh = (lane >> 3) & 1;

    float acc[2][4][4];
#pragma unroll
    for (int mi = 0; mi < 2; ++mi)
#pragma unroll
        for (int ni = 0; ni < 4; ++ni)
#pragma unroll
            for (int r = 0; r < 4; ++r) acc[mi][ni][r] = 0.f;

    // double-buffered fragments
    uint32_t ah[2][2][4], al[2][2][4], bh[2][2][4], bl[2][2][4];

    auto load_frags = [&](uint32_t st, int k, int b) {
#pragma unroll
        for (int mi = 0; mi < 2; ++mi) {
            uint32_t off = (uint32_t)(aRow[mi] * 128 +
                            (((2 * k + aCh) ^ (aRow[mi] & 7)) << 4));
            ldsm_x4(ah[b][mi], st + OFF_A0 + off);
            ldsm_x4(al[b][mi], st + OFF_A1 + off);
        }
#pragma unroll
        for (int g = 0; g < 2; ++g) {
            uint32_t off = (uint32_t)(bRow[g] * 128 +
                            (((2 * k + bCh) ^ (bRow[g] & 7)) << 4));
            ldsm_x4(bh[b][g], st + OFF_B0 + off);
            ldsm_x4(bl[b][g], st + OFF_B1 + off);
        }
    };

    auto do_mmas = [&](int b) {
        // pass-major: 8 independent MMAs between accumulator reuses
#pragma unroll
        for (int mi = 0; mi < 2; ++mi)
#pragma unroll
            for (int ni = 0; ni < 4; ++ni)
                mma_bf16(acc[mi][ni], ah[b][mi], &bh[b][ni >> 1][(ni & 1) * 2]);
#pragma unroll
        for (int mi = 0; mi < 2; ++mi)
#pragma unroll
            for (int ni = 0; ni < 4; ++ni)
                mma_bf16(acc[mi][ni], ah[b][mi], &bl[b][ni >> 1][(ni & 1) * 2]);
#pragma unroll
        for (int mi = 0; mi < 2; ++mi)
#pragma unroll
            for (int ni = 0; ni < 4; ++ni)
                mma_bf16(acc[mi][ni], al[b][mi], &bh[b][ni >> 1][(ni & 1) * 2]);
    };

    const int NS = K / BK;
    load_stage(0, 0);  CP_COMMIT();
    load_stage(BK, 1); CP_COMMIT();

    CP_WAIT(1);
    __syncthreads();
    load_frags(sb, 0, 0);

    for (int i = 0; i < NS; ++i) {
        const int s = i & 1;
        const uint32_t stc = sb + (uint32_t)s * STAGE_BYTES;
#pragma unroll
        for (int k = 0; k < 4; ++k) {
            if (k < 3) load_frags(stc, k + 1, (k + 1) & 1);
            do_mmas(k & 1);
        }
        __syncthreads();                 // all warps done reading stage s
        if (i + 2 < NS) load_stage((i + 2) * BK, s);
        CP_COMMIT();
        if (i + 1 < NS) {
            CP_WAIT(1);
            __syncthreads();
            load_frags(sb + (uint32_t)((i + 1) & 1) * STAGE_BYTES, 0, 0);
        }
    }

    // ---- epilogue: bias add, write fp32 + bf16 hi/lo ----
    const int quad = lane >> 2;
    const int tc = (lane & 3) * 2;
#pragma unroll
    for (int mi = 0; mi < 2; ++mi) {
#pragma unroll
        for (int ni = 0; ni < 4; ++ni) {
            const int col = bn + wn * 32 + ni * 8 + tc;
            const int r0 = bm + wm * 32 + mi * 16 + quad;
            const float2 b2 = *reinterpret_cast<const float2*>(bias + col);
            float2 o0, o1;
            o0.x = acc[mi][ni][0] + b2.x; o0.y = acc[mi][ni][1] + b2.y;
            o1.x = acc[mi][ni][2] + b2.x; o1.y = acc[mi][ni][3] + b2.y;
            *reinterpret_cast<float2*>(Vout + (size_t)r0 * N + col) = o0;
            *reinterpret_cast<float2*>(Vout + (size_t)(r0 + 8) * N + col) = o1;

            __nv_bfloat162 h0, h1, l0, l1;
            h0.x = __float2bfloat16(o0.x); h0.y = __float2bfloat16(o0.y);
            h1.x = __float2bfloat16(o1.x); h1.y = __float2bfloat16(o1.y);
            l0.x = __float2bfloat16(o0.x - __bfloat162float(h0.x));
            l0.y = __float2bfloat16(o0.y - __bfloat162float(h0.y));
            l1.x = __float2bfloat16(o1.x - __bfloat162float(h1.x));
            l1.y = __float2bfloat16(o1.y - __bfloat162float(h1.y));
            *reinterpret_cast<__nv_bfloat162*>(OutHi + (size_t)r0 * N + col) = h0;
            *reinterpret_cast<__nv_bfloat162*>(OutHi + (size_t)(r0 + 8) * N + col) = h1;
            *reinterpret_cast<__nv_bfloat162*>(OutLo + (size_t)r0 * N + col) = l0;
            *reinterpret_cast<__nv_bfloat162*>(OutLo + (size_t)(r0 + 8) * N + col) = l1;
        }
    }
}

// ---------------- fp32 -> bf16 hi/lo split ----------------
__global__ __launch_bounds__(256)
void split_bf16_kernel(const float* __restrict__ src,
                       __nv_bfloat16* __restrict__ hi,
                       __nv_bfloat16* __restrict__ lo,
                       size_t n) {
    size_t i = ((size_t)blockIdx.x * 256 + threadIdx.x) * 4;
    if (i >= n) return;
    float4 x = *reinterpret_cast<const float4*>(src + i);
    __nv_bfloat162 hh0, hh1, ll0, ll1;
    hh0.x = __float2bfloat16(x.x); hh0.y = __float2bfloat16(x.y);
    hh1.x = __float2bfloat16(x.z); hh1.y = __float2bfloat16(x.w);
    ll0.x = __float2bfloat16(x.x - __bfloat162float(hh0.x));
    ll0.y = __float2bfloat16(x.y - __bfloat162float(hh0.y));
    ll1.x = __float2bfloat16(x.z - __bfloat162float(hh1.x));
    ll1.y = __float2bfloat16(x.w - __bfloat162float(hh1.y));
    *reinterpret_cast<__nv_bfloat162*>(hi + i) = hh0;
    *reinterpret_cast<__nv_bfloat162*>(hi + i + 2) = hh1;
    *reinterpret_cast<__nv_bfloat162*>(lo + i) = ll0;
    *reinterpret_cast<__nv_bfloat162*>(lo + i + 2) = ll1;
}

// ---------------- Householder reflection ----------------
__global__ __launch_bounds__(256)
void hflow_kernel(const float* __restrict__ V,
                  const float* __restrict__ Zin,
                  float* __restrict__ Zout, int L) {
    const size_t base = (size_t)blockIdx.x * L;
    const float4* v4 = reinterpret_cast<const float4*>(V + base);
    const float4* z4 = reinterpret_cast<const float4*>(Zin + base);
    float4* o4 = reinterpret_cast<float4*>(Zout + base);
    const int n4 = L >> 2;

    float4 vr[4], zr[4];
    float vz = 0.f, vv = 0.f;
    int cnt = 0;
    for (int idx = threadIdx.x; idx < n4; idx += 256) {
        const float4 v = v4[idx];
        const float4 z = z4[idx];
        vr[cnt] = v; zr[cnt] = z; ++cnt;
        vz += v.x * z.x + v.y * z.y + v.z * z.z + v.w * z.w;
        vv += v.x * v.x + v.y * v.y + v.z * v.z + v.w * v.w;
    }
#pragma unroll
    for (int off = 16; off > 0; off >>= 1) {
        vz += __shfl_xor_sync(0xffffffffu, vz, off);
        vv += __shfl_xor_sync(0xffffffffu, vv, off);
    }
    __shared__ float svz[8], svv[8];
    const int w = threadIdx.x >> 5;
    if ((threadIdx.x & 31) == 0) { svz[w] = vz; svv[w] = vv; }
    __syncthreads();
    float tvz = 0.f, tvv = 0.f;
#pragma unroll
    for (int i = 0; i < 8; ++i) { tvz += svz[i]; tvv += svv[i]; }
    const float s = -2.0f * tvz / tvv;

    cnt = 0;
    for (int idx = threadIdx.x; idx < n4; idx += 256) {
        const float4 v = vr[cnt];
        const float4 z = zr[cnt]; ++cnt;
        o4[idx] = make_float4(z.x + s * v.x, z.y + s * v.y,
                              z.z + s * v.z, z.w + s * v.w);
    }
}

// ---------------- host launcher ----------------
extern "C" void kernel_launch(void* const* d_in, const int* in_sizes, int n_in,
                              void* d_out, int out_size) {
    const float* z      = (const float*)d_in[0];  // [B, L]
    const float* h_last = (const float*)d_in[1];  // [B, H]
    const float* W0     = (const float*)d_in[2];  // [L, H]
    const float* b0     = (const float*)d_in[3];  // [L]
    const float* Ws     = (const float*)d_in[4];  // [NF-1, L, L]
    const float* bs     = (const float*)d_in[5];  // [NF-1, L]

    const int L = in_sizes[3];
    const int B = in_sizes[0] / L;
    const int H = in_sizes[2] / L;
    const int nsteps = in_sizes[5] / L;  // NF - 1

    float* zout = (float*)d_out;

    void *pwh, *pwl, *pah, *pal, *pv;
    cudaGetSymbolAddress(&pwh, g_w_hi);
    cudaGetSymbolAddress(&pwl, g_w_lo);
    cudaGetSymbolAddress(&pah, g_a_hi);
    cudaGetSymbolAddress(&pal, g_a_lo);
    cudaGetSymbolAddress(&pv, g_v);
    __nv_bfloat16* whi = (__nv_bfloat16*)pwh;
    __nv_bfloat16* wlo = (__nv_bfloat16*)pwl;
    __nv_bfloat16* ahi[2] = {(__nv_bfloat16*)pah, (__nv_bfloat16*)pah + (size_t)MAXB * MAXL};
    __nv_bfloat16* alo[2] = {(__nv_bfloat16*)pal, (__nv_bfloat16*)pal + (size_t)MAXB * MAXL};
    float* v = (float*)pv;

    cudaFuncSetAttribute(mma_bf16x3_kernel,
                         cudaFuncAttributeMaxDynamicSharedMemorySize, SMEM_TOTAL);

    // weight + input splits
    {
        size_t n0 = (size_t)L * H;
        split_bf16_kernel<<<(unsigned)(n0 / 4 / 256), 256>>>(W0, whi, wlo, n0);
        size_t nw = (size_t)nsteps * L * L;
        split_bf16_kernel<<<(unsigned)(nw / 4 / 256), 256>>>(Ws, whi + n0, wlo + n0, nw);
        size_t na = (size_t)B * H;
        split_bf16_kernel<<<(unsigned)(na / 4 / 256), 256>>>(h_last, ahi[0], alo[0], na);
    }

    const dim3 gblock(NTHREADS);
    const dim3 ggrid(L / BN, B / BM);

    int cur = 0;
    for (int j = 0; j <= nsteps; ++j) {
        const int K = (j == 0) ? H : L;
        const __nv_bfloat16* wh = whi + ((j == 0) ? 0 : (size_t)L * H + (size_t)(j - 1) * L * L);
        const __nv_bfloat16* wl = wlo + ((j == 0) ? 0 : (size_t)L * H + (size_t)(j - 1) * L * L);
        const float* bias = (j == 0) ? b0 : bs + (size_t)(j - 1) * L;
        const int nxt = cur ^ 1;

        mma_bf16x3_kernel<<<ggrid, gblock, SMEM_TOTAL>>>(
            ahi[cur], alo[cur], wh, wl, bias, v, ahi[nxt], alo[nxt], B, L, K);
        hflow_kernel<<<B, 256>>>(v, (j == 0) ? z : zout, zout, L);
        cur = nxt;
    }
}

// round 6
// speedup vs baseline: 4.3565x; 1.3943x over previous
#include <cuda_runtime.h>
#include <cuda_fp16.h>
#include <cstdint>

// ---------------------------------------------------------------------------
// HouseholderFlow via warp-level mma.sync (HMMA, base sm_103 ISA).
// R5: fp16 2-pass split GEMM.
//   Weights pre-scaled Ws' = 50*W, split Whi+Wlo (fp16 pair ~ 2^-22 accurate).
//   Activations v quantized to single fp16 (2^-11).
//   C = A16 @ (Whi + Wlo)^T  (2 MMA passes, fp32 acc);  v = C/50 + bias.
//   z <- z - 2 v (v.z)/||v||^2 per row (scale-invariant in v).
// ---------------------------------------------------------------------------

#define BM 128
#define BN 64
#define BK 64
#define NTHREADS 256
#define NSTAGES 3

#define OFF_A  0
#define OFF_B0 16384
#define OFF_B1 24576
#define STAGE_BYTES 32768
#define SMEM_TOTAL (NSTAGES * STAGE_BYTES)

#define MAXB 8192
#define MAXL 2048
#define MAXNF 8
#define WSCALE 50.0f
#define WSCALE_INV (1.0f / 50.0f)

__device__ __half g_w_hi[(size_t)MAXNF * MAXL * MAXL];
__device__ __half g_w_lo[(size_t)MAXNF * MAXL * MAXL];
__device__ __half g_a16[2][(size_t)MAXB * MAXL];
__device__ float g_v[(size_t)MAXB * MAXL];

// ---------------- PTX helpers (base ISA only) ----------------

__device__ __forceinline__ uint32_t smem_u32(const void* p) {
    uint32_t a;
    asm("{ .reg .u64 t; cvta.to.shared.u64 t, %1; cvt.u32.u64 %0, t; }"
        : "=r"(a) : "l"(p));
    return a;
}

__device__ __forceinline__ void cp_async_16(uint32_t saddr, const void* gaddr) {
    asm volatile("cp.async.cg.shared.global [%0], [%1], 16;" :: "r"(saddr), "l"(gaddr));
}
#define CP_COMMIT() asm volatile("cp.async.commit_group;" ::: "memory")
#define CP_WAIT(n)  asm volatile("cp.async.wait_group %0;" :: "n"(n) : "memory")

__device__ __forceinline__ void ldsm_x4(uint32_t* r, uint32_t addr) {
    asm volatile("ldmatrix.sync.aligned.m8n8.x4.shared.b16 {%0,%1,%2,%3}, [%4];"
                 : "=r"(r[0]), "=r"(r[1]), "=r"(r[2]), "=r"(r[3]) : "r"(addr));
}

__device__ __forceinline__ void mma_fp16(float* d, const uint32_t* a, const uint32_t* b) {
    asm volatile(
        "mma.sync.aligned.m16n8k16.row.col.f32.f16.f16.f32 "
        "{%0,%1,%2,%3}, {%4,%5,%6,%7}, {%8,%9}, {%0,%1,%2,%3};"
        : "+f"(d[0]), "+f"(d[1]), "+f"(d[2]), "+f"(d[3])
        : "r"(a[0]), "r"(a[1]), "r"(a[2]), "r"(a[3]), "r"(b[0]), "r"(b[1]));
}

// ---------------- GEMM kernel ----------------
// C[m,n] = sum_k A16[m,k]*(Whi[n,k]+Wlo[n,k]); out v = C/50 + bias[n].
// Writes v as fp32 (Vout) and fp16 (OutA16) for the next GEMM.
__global__ __launch_bounds__(NTHREADS, 2)
void mma_fp16x2_kernel(const __half* __restrict__ A16,
                       const __half* __restrict__ Whi,
                       const __half* __restrict__ Wlo,
                       const float* __restrict__ bias,
                       float* __restrict__ Vout,
                       __half* __restrict__ OutA16,
                       int M, int N, int K) {
    extern __shared__ __align__(1024) char smem_raw[];
    const uint32_t sb = smem_u32(smem_raw);

    const int tid = threadIdx.x;
    const int lane = tid & 31;
    const int wid = tid >> 5;
    const int wm = wid & 3;   // 4 warps along M: 4*32 = 128
    const int wn = wid >> 2;  // 2 warps along N: 2*32 = 64
    const int bm = blockIdx.y * BM;
    const int bn = blockIdx.x * BN;

    // ---- cp.async stage loader: rows x 64 fp16 (128B), XOR swizzle ----
    auto load_stage = [&](int k0, int s) {
        const uint32_t st = sb + (uint32_t)s * STAGE_BYTES;
#pragma unroll
        for (int it = 0; it < 4; ++it) {              // A: 128 rows * 8 chunks
            int q = tid + it * NTHREADS;
            int row = q >> 3, kc = q & 7;
            uint32_t so = (uint32_t)(row * 128 + ((kc ^ (row & 7)) << 4));
            size_t ge = (size_t)(bm + row) * K + k0 + kc * 8;
            cp_async_16(st + OFF_A + so, A16 + ge);
        }
#pragma unroll
        for (int it = 0; it < 2; ++it) {              // B: 64 rows * 8 chunks
            int q = tid + it * NTHREADS;
            int row = q >> 3, kc = q & 7;
            uint32_t so = (uint32_t)(row * 128 + ((kc ^ (row & 7)) << 4));
            size_t ge = (size_t)(bn + row) * K + k0 + kc * 8;
            cp_async_16(st + OFF_B0 + so, Whi + ge);
            cp_async_16(st + OFF_B1 + so, Wlo + ge);
        }
    };

    // ---- per-lane ldmatrix address components ----
    int aRow[2], bRow[2];
#pragma unroll
    for (int mi = 0; mi < 2; ++mi) aRow[mi] = wm * 32 + mi * 16 + (lane & 15);
#pragma unroll
    for (int g = 0; g < 2; ++g)
        bRow[g] = wn * 32 + g * 16 + ((lane >> 4) << 3) + (lane & 7);
    const int aCh = lane >> 4;
    const int bCh = (lane >> 3) & 1;

    float acc[2][4][4];
#pragma unroll
    for (int mi = 0; mi < 2; ++mi)
#pragma unroll
        for (int ni = 0; ni < 4; ++ni)
#pragma unroll
            for (int r = 0; r < 4; ++r) acc[mi][ni][r] = 0.f;

    // double-buffered fragments
    uint32_t af[2][2][4], bh[2][2][4], bl[2][2][4];

    auto load_frags = [&](uint32_t st, int k, int b) {
#pragma unroll
        for (int mi = 0; mi < 2; ++mi) {
            uint32_t off = (uint32_t)(aRow[mi] * 128 +
                            (((2 * k + aCh) ^ (aRow[mi] & 7)) << 4));
            ldsm_x4(af[b][mi], st + OFF_A + off);
        }
#pragma unroll
        for (int g = 0; g < 2; ++g) {
            uint32_t off = (uint32_t)(bRow[g] * 128 +
                            (((2 * k + bCh) ^ (bRow[g] & 7)) << 4));
            ldsm_x4(bh[b][g], st + OFF_B0 + off);
            ldsm_x4(bl[b][g], st + OFF_B1 + off);
        }
    };

    auto do_mmas = [&](int b) {
        // pass-major: 8 independent MMAs between accumulator reuses
#pragma unroll
        for (int mi = 0; mi < 2; ++mi)
#pragma unroll
            for (int ni = 0; ni < 4; ++ni)
                mma_fp16(acc[mi][ni], af[b][mi], &bh[b][ni >> 1][(ni & 1) * 2]);
#pragma unroll
        for (int mi = 0; mi < 2; ++mi)
#pragma unroll
            for (int ni = 0; ni < 4; ++ni)
                mma_fp16(acc[mi][ni], af[b][mi], &bl[b][ni >> 1][(ni & 1) * 2]);
    };

    const int NS = K / BK;
    load_stage(0, 0);  CP_COMMIT();
    load_stage(BK, 1); CP_COMMIT();

    for (int i = 0; i < NS; ++i) {
        const int s = i % NSTAGES;
        const uint32_t stc = sb + (uint32_t)s * STAGE_BYTES;
        CP_WAIT(1);            // per-thread: group for stage i complete
        __syncthreads();       // all threads' stage-i data visible; slot (i-1)%3 free
        if (i + 2 < NS) load_stage((i + 2) * BK, (i + 2) % NSTAGES);
        CP_COMMIT();           // always commit (empty groups keep numbering uniform)

        load_frags(stc, 0, 0);
#pragma unroll
        for (int k = 0; k < 4; ++k) {
            if (k < 3) load_frags(stc, k + 1, (k + 1) & 1);
            do_mmas(k & 1);
        }
    }

    // ---- epilogue: scale, bias add, write fp32 + fp16 ----
    const int quad = lane >> 2;
    const int tc = (lane & 3) * 2;
#pragma unroll
    for (int mi = 0; mi < 2; ++mi) {
#pragma unroll
        for (int ni = 0; ni < 4; ++ni) {
            const int col = bn + wn * 32 + ni * 8 + tc;
            const int r0 = bm + wm * 32 + mi * 16 + quad;
            const float2 b2 = *reinterpret_cast<const float2*>(bias + col);
            float2 o0, o1;
            o0.x = acc[mi][ni][0] * WSCALE_INV + b2.x;
            o0.y = acc[mi][ni][1] * WSCALE_INV + b2.y;
            o1.x = acc[mi][ni][2] * WSCALE_INV + b2.x;
            o1.y = acc[mi][ni][3] * WSCALE_INV + b2.y;
            *reinterpret_cast<float2*>(Vout + (size_t)r0 * N + col) = o0;
            *reinterpret_cast<float2*>(Vout + (size_t)(r0 + 8) * N + col) = o1;

            __half2 h0, h1;
            h0.x = __float2half_rn(o0.x); h0.y = __float2half_rn(o0.y);
            h1.x = __float2half_rn(o1.x); h1.y = __float2half_rn(o1.y);
            *reinterpret_cast<__half2*>(OutA16 + (size_t)r0 * N + col) = h0;
            *reinterpret_cast<__half2*>(OutA16 + (size_t)(r0 + 8) * N + col) = h1;
        }
    }
}

// ---------------- fp32 -> scaled fp16 hi/lo split (weights) ----------------
__global__ __launch_bounds__(256)
void split_w_kernel(const float* __restrict__ src,
                    __half* __restrict__ hi,
                    __half* __restrict__ lo,
                    size_t n) {
    size_t i = ((size_t)blockIdx.x * 256 + threadIdx.x) * 4;
    if (i >= n) return;
    float4 x = *reinterpret_cast<const float4*>(src + i);
    x.x *= WSCALE; x.y *= WSCALE; x.z *= WSCALE; x.w *= WSCALE;
    __half2 hh0, hh1, ll0, ll1;
    hh0.x = __float2half_rn(x.x); hh0.y = __float2half_rn(x.y);
    hh1.x = __float2half_rn(x.z); hh1.y = __float2half_rn(x.w);
    ll0.x = __float2half_rn(x.x - __half2float(hh0.x));
    ll0.y = __float2half_rn(x.y - __half2float(hh0.y));
    ll1.x = __float2half_rn(x.z - __half2float(hh1.x));
    ll1.y = __float2half_rn(x.w - __half2float(hh1.y));
    *reinterpret_cast<__half2*>(hi + i) = hh0;
    *reinterpret_cast<__half2*>(hi + i + 2) = hh1;
    *reinterpret_cast<__half2*>(lo + i) = ll0;
    *reinterpret_cast<__half2*>(lo + i + 2) = ll1;
}

// ---------------- fp32 -> fp16 convert (activations) ----------------
__global__ __launch_bounds__(256)
void cvt_fp16_kernel(const float* __restrict__ src,
                     __half* __restrict__ dst, size_t n) {
    size_t i = ((size_t)blockIdx.x * 256 + threadIdx.x) * 4;
    if (i >= n) return;
    float4 x = *reinterpret_cast<const float4*>(src + i);
    __half2 h0, h1;
    h0.x = __float2half_rn(x.x); h0.y = __float2half_rn(x.y);
    h1.x = __float2half_rn(x.z); h1.y = __float2half_rn(x.w);
    *reinterpret_cast<__half2*>(dst + i) = h0;
    *reinterpret_cast<__half2*>(dst + i + 2) = h1;
}

// ---------------- Householder reflection ----------------
__global__ __launch_bounds__(256)
void hflow_kernel(const float* __restrict__ V,
                  const float* __restrict__ Zin,
                  float* __restrict__ Zout, int L) {
    const size_t base = (size_t)blockIdx.x * L;
    const float4* v4 = reinterpret_cast<const float4*>(V + base);
    const float4* z4 = reinterpret_cast<const float4*>(Zin + base);
    float4* o4 = reinterpret_cast<float4*>(Zout + base);
    const int n4 = L >> 2;

    float4 vr[4], zr[4];
    float vz = 0.f, vv = 0.f;
    int cnt = 0;
    for (int idx = threadIdx.x; idx < n4; idx += 256) {
        const float4 v = v4[idx];
        const float4 z = z4[idx];
        vr[cnt] = v; zr[cnt] = z; ++cnt;
        vz += v.x * z.x + v.y * z.y + v.z * z.z + v.w * z.w;
        vv += v.x * v.x + v.y * v.y + v.z * v.z + v.w * v.w;
    }
#pragma unroll
    for (int off = 16; off > 0; off >>= 1) {
        vz += __shfl_xor_sync(0xffffffffu, vz, off);
        vv += __shfl_xor_sync(0xffffffffu, vv, off);
    }
    __shared__ float svz[8], svv[8];
    const int w = threadIdx.x >> 5;
    if ((threadIdx.x & 31) == 0) { svz[w] = vz; svv[w] = vv; }
    __syncthreads();
    float tvz = 0.f, tvv = 0.f;
#pragma unroll
    for (int i = 0; i < 8; ++i) { tvz += svz[i]; tvv += svv[i]; }
    const float s = -2.0f * tvz / tvv;

    cnt = 0;
    for (int idx = threadIdx.x; idx < n4; idx += 256) {
        const float4 v = vr[cnt];
        const float4 z = zr[cnt]; ++cnt;
        o4[idx] = make_float4(z.x + s * v.x, z.y + s * v.y,
                              z.z + s * v.z, z.w + s * v.w);
    }
}

// ---------------- host launcher ----------------
extern "C" void kernel_launch(void* const* d_in, const int* in_sizes, int n_in,
                              void* d_out, int out_size) {
    const float* z      = (const float*)d_in[0];  // [B, L]
    const float* h_last = (const float*)d_in[1];  // [B, H]
    const float* W0     = (const float*)d_in[2];  // [L, H]
    const float* b0     = (const float*)d_in[3];  // [L]
    const float* Ws     = (const float*)d_in[4];  // [NF-1, L, L]
    const float* bs     = (const float*)d_in[5];  // [NF-1, L]

    const int L = in_sizes[3];
    const int B = in_sizes[0] / L;
    const int H = in_sizes[2] / L;
    const int nsteps = in_sizes[5] / L;  // NF - 1

    float* zout = (float*)d_out;

    void *pwh, *pwl, *pa, *pv;
    cudaGetSymbolAddress(&pwh, g_w_hi);
    cudaGetSymbolAddress(&pwl, g_w_lo);
    cudaGetSymbolAddress(&pa, g_a16);
    cudaGetSymbolAddress(&pv, g_v);
    __half* whi = (__half*)pwh;
    __half* wlo = (__half*)pwl;
    __half* a16[2] = {(__half*)pa, (__half*)pa + (size_t)MAXB * MAXL};
    float* v = (float*)pv;

    cudaFuncSetAttribute(mma_fp16x2_kernel,
                         cudaFuncAttributeMaxDynamicSharedMemorySize, SMEM_TOTAL);

    // weight splits (scaled by 50) + first activation convert
    {
        size_t n0 = (size_t)L * H;
        split_w_kernel<<<(unsigned)(n0 / 4 / 256), 256>>>(W0, whi, wlo, n0);
        size_t nw = (size_t)nsteps * L * L;
        split_w_kernel<<<(unsigned)(nw / 4 / 256), 256>>>(Ws, whi + n0, wlo + n0, nw);
        size_t na = (size_t)B * H;
        cvt_fp16_kernel<<<(unsigned)(na / 4 / 256), 256>>>(h_last, a16[0], na);
    }

    const dim3 gblock(NTHREADS);
    const dim3 ggrid(L / BN, B / BM);

    int cur = 0;
    for (int j = 0; j <= nsteps; ++j) {
        const int K = (j == 0) ? H : L;
        const __half* wh = whi + ((j == 0) ? 0 : (size_t)L * H + (size_t)(j - 1) * L * L);
        const __half* wl = wlo + ((j == 0) ? 0 : (size_t)L * H + (size_t)(j - 1) * L * L);
        const float* bias = (j == 0) ? b0 : bs + (size_t)(j - 1) * L;
        const int nxt = cur ^ 1;

        mma_fp16x2_kernel<<<ggrid, gblock, SMEM_TOTAL>>>(
            a16[cur], wh, wl, bias, v, a16[nxt], B, L, K);
        hflow_kernel<<<B, 256>>>(v, (j == 0) ? z : zout, zout, L);
        cur = nxt;
    }
}

// round 7
// speedup vs baseline: 4.3666x; 1.0023x over previous
#include <cuda_runtime.h>
#include <cuda_fp16.h>
#include <cstdint>

// ---------------------------------------------------------------------------
// HouseholderFlow via warp-level mma.sync (HMMA, base sm_103 ISA).
// R5: fp16 2-pass split GEMM.
//   Weights pre-scaled Ws' = 50*W, split Whi+Wlo (fp16 pair ~ 2^-22 accurate).
//   Activations v quantized to single fp16 (2^-11).
//   C = A16 @ (Whi + Wlo)^T  (2 MMA passes, fp32 acc);  v = C/50 + bias.
//   z <- z - 2 v (v.z)/||v||^2 per row (scale-invariant in v).
// ---------------------------------------------------------------------------

#define BM 128
#define BN 64
#define BK 64
#define NTHREADS 256
#define NSTAGES 3

#define OFF_A  0
#define OFF_B0 16384
#define OFF_B1 24576
#define STAGE_BYTES 32768
#define SMEM_TOTAL (NSTAGES * STAGE_BYTES)

#define MAXB 8192
#define MAXL 2048
#define MAXNF 8
#define WSCALE 50.0f
#define WSCALE_INV (1.0f / 50.0f)

__device__ __half g_w_hi[(size_t)MAXNF * MAXL * MAXL];
__device__ __half g_w_lo[(size_t)MAXNF * MAXL * MAXL];
__device__ __half g_a16[2][(size_t)MAXB * MAXL];
__device__ float g_v[(size_t)MAXB * MAXL];

// ---------------- PTX helpers (base ISA only) ----------------

__device__ __forceinline__ uint32_t smem_u32(const void* p) {
    uint32_t a;
    asm("{ .reg .u64 t; cvta.to.shared.u64 t, %1; cvt.u32.u64 %0, t; }"
        : "=r"(a) : "l"(p));
    return a;
}

__device__ __forceinline__ void cp_async_16(uint32_t saddr, const void* gaddr) {
    asm volatile("cp.async.cg.shared.global [%0], [%1], 16;" :: "r"(saddr), "l"(gaddr));
}
#define CP_COMMIT() asm volatile("cp.async.commit_group;" ::: "memory")
#define CP_WAIT(n)  asm volatile("cp.async.wait_group %0;" :: "n"(n) : "memory")

__device__ __forceinline__ void ldsm_x4(uint32_t* r, uint32_t addr) {
    asm volatile("ldmatrix.sync.aligned.m8n8.x4.shared.b16 {%0,%1,%2,%3}, [%4];"
                 : "=r"(r[0]), "=r"(r[1]), "=r"(r[2]), "=r"(r[3]) : "r"(addr));
}

__device__ __forceinline__ void mma_fp16(float* d, const uint32_t* a, const uint32_t* b) {
    asm volatile(
        "mma.sync.aligned.m16n8k16.row.col.f32.f16.f16.f32 "
        "{%0,%1,%2,%3}, {%4,%5,%6,%7}, {%8,%9}, {%0,%1,%2,%3};"
        : "+f"(d[0]), "+f"(d[1]), "+f"(d[2]), "+f"(d[3])
        : "r"(a[0]), "r"(a[1]), "r"(a[2]), "r"(a[3]), "r"(b[0]), "r"(b[1]));
}

// ---------------- GEMM kernel ----------------
// C[m,n] = sum_k A16[m,k]*(Whi[n,k]+Wlo[n,k]); out v = C/50 + bias[n].
// Writes v as fp32 (Vout) and fp16 (OutA16) for the next GEMM.
__global__ __launch_bounds__(NTHREADS, 2)
void mma_fp16x2_kernel(const __half* __restrict__ A16,
                       const __half* __restrict__ Whi,
                       const __half* __restrict__ Wlo,
                       const float* __restrict__ bias,
                       float* __restrict__ Vout,
                       __half* __restrict__ OutA16,
                       int M, int N, int K) {
    extern __shared__ __align__(1024) char smem_raw[];
    const uint32_t sb = smem_u32(smem_raw);

    const int tid = threadIdx.x;
    const int lane = tid & 31;
    const int wid = tid >> 5;
    const int wm = wid & 3;   // 4 warps along M: 4*32 = 128
    const int wn = wid >> 2;  // 2 warps along N: 2*32 = 64
    const int bm = blockIdx.y * BM;
    const int bn = blockIdx.x * BN;

    // ---- cp.async stage loader: rows x 64 fp16 (128B), XOR swizzle ----
    auto load_stage = [&](int k0, int s) {
        const uint32_t st = sb + (uint32_t)s * STAGE_BYTES;
#pragma unroll
        for (int it = 0; it < 4; ++it) {              // A: 128 rows * 8 chunks
            int q = tid + it * NTHREADS;
            int row = q >> 3, kc = q & 7;
            uint32_t so = (uint32_t)(row * 128 + ((kc ^ (row & 7)) << 4));
            size_t ge = (size_t)(bm + row) * K + k0 + kc * 8;
            cp_async_16(st + OFF_A + so, A16 + ge);
        }
#pragma unroll
        for (int it = 0; it < 2; ++it) {              // B: 64 rows * 8 chunks
            int q = tid + it * NTHREADS;
            int row = q >> 3, kc = q & 7;
            uint32_t so = (uint32_t)(row * 128 + ((kc ^ (row & 7)) << 4));
            size_t ge = (size_t)(bn + row) * K + k0 + kc * 8;
            cp_async_16(st + OFF_B0 + so, Whi + ge);
            cp_async_16(st + OFF_B1 + so, Wlo + ge);
        }
    };

    // ---- per-lane ldmatrix address components ----
    int aRow[2], bRow[2];
#pragma unroll
    for (int mi = 0; mi < 2; ++mi) aRow[mi] = wm * 32 + mi * 16 + (lane & 15);
#pragma unroll
    for (int g = 0; g < 2; ++g)
        bRow[g] = wn * 32 + g * 16 + ((lane >> 4) << 3) + (lane & 7);
    const int aCh = lane >> 4;
    const int bCh = (lane >> 3) & 1;

    float acc[2][4][4];
#pragma unroll
    for (int mi = 0; mi < 2; ++mi)
#pragma unroll
        for (int ni = 0; ni < 4; ++ni)
#pragma unroll
            for (int r = 0; r < 4; ++r) acc[mi][ni][r] = 0.f;

    // double-buffered fragments
    uint32_t af[2][2][4], bh[2][2][4], bl[2][2][4];

    auto load_frags = [&](uint32_t st, int k, int b) {
#pragma unroll
        for (int mi = 0; mi < 2; ++mi) {
            uint32_t off = (uint32_t)(aRow[mi] * 128 +
                            (((2 * k + aCh) ^ (aRow[mi] & 7)) << 4));
            ldsm_x4(af[b][mi], st + OFF_A + off);
        }
#pragma unroll
        for (int g = 0; g < 2; ++g) {
            uint32_t off = (uint32_t)(bRow[g] * 128 +
                            (((2 * k + bCh) ^ (bRow[g] & 7)) << 4));
            ldsm_x4(bh[b][g], st + OFF_B0 + off);
            ldsm_x4(bl[b][g], st + OFF_B1 + off);
        }
    };

    auto do_mmas = [&](int b) {
        // pass-major: 8 independent MMAs between accumulator reuses
#pragma unroll
        for (int mi = 0; mi < 2; ++mi)
#pragma unroll
            for (int ni = 0; ni < 4; ++ni)
                mma_fp16(acc[mi][ni], af[b][mi], &bh[b][ni >> 1][(ni & 1) * 2]);
#pragma unroll
        for (int mi = 0; mi < 2; ++mi)
#pragma unroll
            for (int ni = 0; ni < 4; ++ni)
                mma_fp16(acc[mi][ni], af[b][mi], &bl[b][ni >> 1][(ni & 1) * 2]);
    };

    const int NS = K / BK;
    load_stage(0, 0);  CP_COMMIT();
    load_stage(BK, 1); CP_COMMIT();

    for (int i = 0; i < NS; ++i) {
        const int s = i % NSTAGES;
        const uint32_t stc = sb + (uint32_t)s * STAGE_BYTES;
        CP_WAIT(1);            // per-thread: group for stage i complete
        __syncthreads();       // all threads' stage-i data visible; slot (i-1)%3 free
        if (i + 2 < NS) load_stage((i + 2) * BK, (i + 2) % NSTAGES);
        CP_COMMIT();           // always commit (empty groups keep numbering uniform)

        load_frags(stc, 0, 0);
#pragma unroll
        for (int k = 0; k < 4; ++k) {
            if (k < 3) load_frags(stc, k + 1, (k + 1) & 1);
            do_mmas(k & 1);
        }
    }

    // ---- epilogue: scale, bias add, write fp32 + fp16 ----
    const int quad = lane >> 2;
    const int tc = (lane & 3) * 2;
#pragma unroll
    for (int mi = 0; mi < 2; ++mi) {
#pragma unroll
        for (int ni = 0; ni < 4; ++ni) {
            const int col = bn + wn * 32 + ni * 8 + tc;
            const int r0 = bm + wm * 32 + mi * 16 + quad;
            const float2 b2 = *reinterpret_cast<const float2*>(bias + col);
            float2 o0, o1;
            o0.x = acc[mi][ni][0] * WSCALE_INV + b2.x;
            o0.y = acc[mi][ni][1] * WSCALE_INV + b2.y;
            o1.x = acc[mi][ni][2] * WSCALE_INV + b2.x;
            o1.y = acc[mi][ni][3] * WSCALE_INV + b2.y;
            *reinterpret_cast<float2*>(Vout + (size_t)r0 * N + col) = o0;
            *reinterpret_cast<float2*>(Vout + (size_t)(r0 + 8) * N + col) = o1;

            __half2 h0, h1;
            h0.x = __float2half_rn(o0.x); h0.y = __float2half_rn(o0.y);
            h1.x = __float2half_rn(o1.x); h1.y = __float2half_rn(o1.y);
            *reinterpret_cast<__half2*>(OutA16 + (size_t)r0 * N + col) = h0;
            *reinterpret_cast<__half2*>(OutA16 + (size_t)(r0 + 8) * N + col) = h1;
        }
    }
}

// ---------------- fp32 -> scaled fp16 hi/lo split (weights) ----------------
__global__ __launch_bounds__(256)
void split_w_kernel(const float* __restrict__ src,
                    __half* __restrict__ hi,
                    __half* __restrict__ lo,
                    size_t n) {
    size_t i = ((size_t)blockIdx.x * 256 + threadIdx.x) * 4;
    if (i >= n) return;
    float4 x = *reinterpret_cast<const float4*>(src + i);
    x.x *= WSCALE; x.y *= WSCALE; x.z *= WSCALE; x.w *= WSCALE;
    __half2 hh0, hh1, ll0, ll1;
    hh0.x = __float2half_rn(x.x); hh0.y = __float2half_rn(x.y);
    hh1.x = __float2half_rn(x.z); hh1.y = __float2half_rn(x.w);
    ll0.x = __float2half_rn(x.x - __half2float(hh0.x));
    ll0.y = __float2half_rn(x.y - __half2float(hh0.y));
    ll1.x = __float2half_rn(x.z - __half2float(hh1.x));
    ll1.y = __float2half_rn(x.w - __half2float(hh1.y));
    *reinterpret_cast<__half2*>(hi + i) = hh0;
    *reinterpret_cast<__half2*>(hi + i + 2) = hh1;
    *reinterpret_cast<__half2*>(lo + i) = ll0;
    *reinterpret_cast<__half2*>(lo + i + 2) = ll1;
}

// ---------------- fp32 -> fp16 convert (activations) ----------------
__global__ __launch_bounds__(256)
void cvt_fp16_kernel(const float* __restrict__ src,
                     __half* __restrict__ dst, size_t n) {
    size_t i = ((size_t)blockIdx.x * 256 + threadIdx.x) * 4;
    if (i >= n) return;
    float4 x = *reinterpret_cast<const float4*>(src + i);
    __half2 h0, h1;
    h0.x = __float2half_rn(x.x); h0.y = __float2half_rn(x.y);
    h1.x = __float2half_rn(x.z); h1.y = __float2half_rn(x.w);
    *reinterpret_cast<__half2*>(dst + i) = h0;
    *reinterpret_cast<__half2*>(dst + i + 2) = h1;
}

// ---------------- Householder reflection ----------------
__global__ __launch_bounds__(256)
void hflow_kernel(const float* __restrict__ V,
                  const float* __restrict__ Zin,
                  float* __restrict__ Zout, int L) {
    const size_t base = (size_t)blockIdx.x * L;
    const float4* v4 = reinterpret_cast<const float4*>(V + base);
    const float4* z4 = reinterpret_cast<const float4*>(Zin + base);
    float4* o4 = reinterpret_cast<float4*>(Zout + base);
    const int n4 = L >> 2;

    float4 vr[4], zr[4];
    float vz = 0.f, vv = 0.f;
    int cnt = 0;
    for (int idx = threadIdx.x; idx < n4; idx += 256) {
        const float4 v = v4[idx];
        const float4 z = z4[idx];
        vr[cnt] = v; zr[cnt] = z; ++cnt;
        vz += v.x * z.x + v.y * z.y + v.z * z.z + v.w * z.w;
        vv += v.x * v.x + v.y * v.y + v.z * v.z + v.w * v.w;
    }
#pragma unroll
    for (int off = 16; off > 0; off >>= 1) {
        vz += __shfl_xor_sync(0xffffffffu, vz, off);
        vv += __shfl_xor_sync(0xffffffffu, vv, off);
    }
    __shared__ float svz[8], svv[8];
    const int w = threadIdx.x >> 5;
    if ((threadIdx.x & 31) == 0) { svz[w] = vz; svv[w] = vv; }
    __syncthreads();
    float tvz = 0.f, tvv = 0.f;
#pragma unroll
    for (int i = 0; i < 8; ++i) { tvz += svz[i]; tvv += svv[i]; }
    const float s = -2.0f * tvz / tvv;

    cnt = 0;
    for (int idx = threadIdx.x; idx < n4; idx += 256) {
        const float4 v = vr[cnt];
        const float4 z = zr[cnt]; ++cnt;
        o4[idx] = make_float4(z.x + s * v.x, z.y + s * v.y,
                              z.z + s * v.z, z.w + s * v.w);
    }
}

// ---------------- host launcher ----------------
extern "C" void kernel_launch(void* const* d_in, const int* in_sizes, int n_in,
                              void* d_out, int out_size) {
    const float* z      = (const float*)d_in[0];  // [B, L]
    const float* h_last = (const float*)d_in[1];  // [B, H]
    const float* W0     = (const float*)d_in[2];  // [L, H]
    const float* b0     = (const float*)d_in[3];  // [L]
    const float* Ws     = (const float*)d_in[4];  // [NF-1, L, L]
    const float* bs     = (const float*)d_in[5];  // [NF-1, L]

    const int L = in_sizes[3];
    const int B = in_sizes[0] / L;
    const int H = in_sizes[2] / L;
    const int nsteps = in_sizes[5] / L;  // NF - 1

    float* zout = (float*)d_out;

    void *pwh, *pwl, *pa, *pv;
    cudaGetSymbolAddress(&pwh, g_w_hi);
    cudaGetSymbolAddress(&pwl, g_w_lo);
    cudaGetSymbolAddress(&pa, g_a16);
    cudaGetSymbolAddress(&pv, g_v);
    __half* whi = (__half*)pwh;
    __half* wlo = (__half*)pwl;
    __half* a16[2] = {(__half*)pa, (__half*)pa + (size_t)MAXB * MAXL};
    float* v = (float*)pv;

    cudaFuncSetAttribute(mma_fp16x2_kernel,
                         cudaFuncAttributeMaxDynamicSharedMemorySize, SMEM_TOTAL);

    // weight splits (scaled by 50) + first activation convert
    {
        size_t n0 = (size_t)L * H;
        split_w_kernel<<<(unsigned)(n0 / 4 / 256), 256>>>(W0, whi, wlo, n0);
        size_t nw = (size_t)nsteps * L * L;
        split_w_kernel<<<(unsigned)(nw / 4 / 256), 256>>>(Ws, whi + n0, wlo + n0, nw);
        size_t na = (size_t)B * H;
        cvt_fp16_kernel<<<(unsigned)(na / 4 / 256), 256>>>(h_last, a16[0], na);
    }

    const dim3 gblock(NTHREADS);
    const dim3 ggrid(L / BN, B / BM);

    int cur = 0;
    for (int j = 0; j <= nsteps; ++j) {
        const int K = (j == 0) ? H : L;
        const __half* wh = whi + ((j == 0) ? 0 : (size_t)L * H + (size_t)(j - 1) * L * L);
        const __half* wl = wlo + ((j == 0) ? 0 : (size_t)L * H + (size_t)(j - 1) * L * L);
        const float* bias = (j == 0) ? b0 : bs + (size_t)(j - 1) * L;
        const int nxt = cur ^ 1;

        mma_fp16x2_kernel<<<ggrid, gblock, SMEM_TOTAL>>>(
            a16[cur], wh, wl, bias, v, a16[nxt], B, L, K);
        hflow_kernel<<<B, 256>>>(v, (j == 0) ? z : zout, zout, L);
        cur = nxt;
    }
}

// round 9
// speedup vs baseline: 4.3711x; 1.0010x over previous
#include <cuda_runtime.h>
#include <cuda_fp16.h>
#include <cstdint>

// ---------------------------------------------------------------------------
// HouseholderFlow via warp-level mma.sync (HMMA, base sm_103 ISA).
// R5: fp16 2-pass split GEMM.
//   Weights pre-scaled Ws' = 50*W, split Whi+Wlo (fp16 pair ~ 2^-22 accurate).
//   Activations v quantized to single fp16 (2^-11).
//   C = A16 @ (Whi + Wlo)^T  (2 MMA passes, fp32 acc);  v = C/50 + bias.
//   z <- z - 2 v (v.z)/||v||^2 per row (scale-invariant in v).
// ---------------------------------------------------------------------------

#define BM 128
#define BN 64
#define BK 64
#define NTHREADS 256
#define NSTAGES 3

#define OFF_A  0
#define OFF_B0 16384
#define OFF_B1 24576
#define STAGE_BYTES 32768
#define SMEM_TOTAL (NSTAGES * STAGE_BYTES)

#define MAXB 8192
#define MAXL 2048
#define MAXNF 8
#define WSCALE 50.0f
#define WSCALE_INV (1.0f / 50.0f)

__device__ __half g_w_hi[(size_t)MAXNF * MAXL * MAXL];
__device__ __half g_w_lo[(size_t)MAXNF * MAXL * MAXL];
__device__ __half g_a16[2][(size_t)MAXB * MAXL];
__device__ float g_v[(size_t)MAXB * MAXL];

// ---------------- PTX helpers (base ISA only) ----------------

__device__ __forceinline__ uint32_t smem_u32(const void* p) {
    uint32_t a;
    asm("{ .reg .u64 t; cvta.to.shared.u64 t, %1; cvt.u32.u64 %0, t; }"
        : "=r"(a) : "l"(p));
    return a;
}

__device__ __forceinline__ void cp_async_16(uint32_t saddr, const void* gaddr) {
    asm volatile("cp.async.cg.shared.global [%0], [%1], 16;" :: "r"(saddr), "l"(gaddr));
}
#define CP_COMMIT() asm volatile("cp.async.commit_group;" ::: "memory")
#define CP_WAIT(n)  asm volatile("cp.async.wait_group %0;" :: "n"(n) : "memory")

__device__ __forceinline__ void ldsm_x4(uint32_t* r, uint32_t addr) {
    asm volatile("ldmatrix.sync.aligned.m8n8.x4.shared.b16 {%0,%1,%2,%3}, [%4];"
                 : "=r"(r[0]), "=r"(r[1]), "=r"(r[2]), "=r"(r[3]) : "r"(addr));
}

__device__ __forceinline__ void mma_fp16(float* d, const uint32_t* a, const uint32_t* b) {
    asm volatile(
        "mma.sync.aligned.m16n8k16.row.col.f32.f16.f16.f32 "
        "{%0,%1,%2,%3}, {%4,%5,%6,%7}, {%8,%9}, {%0,%1,%2,%3};"
        : "+f"(d[0]), "+f"(d[1]), "+f"(d[2]), "+f"(d[3])
        : "r"(a[0]), "r"(a[1]), "r"(a[2]), "r"(a[3]), "r"(b[0]), "r"(b[1]));
}

// ---------------- GEMM kernel ----------------
// C[m,n] = sum_k A16[m,k]*(Whi[n,k]+Wlo[n,k]); out v = C/50 + bias[n].
// Writes v as fp32 (Vout) and fp16 (OutA16) for the next GEMM.
__global__ __launch_bounds__(NTHREADS, 2)
void mma_fp16x2_kernel(const __half* __restrict__ A16,
                       const __half* __restrict__ Whi,
                       const __half* __restrict__ Wlo,
                       const float* __restrict__ bias,
                       float* __restrict__ Vout,
                       __half* __restrict__ OutA16,
                       int M, int N, int K) {
    extern __shared__ __align__(1024) char smem_raw[];
    const uint32_t sb = smem_u32(smem_raw);

    const int tid = threadIdx.x;
    const int lane = tid & 31;
    const int wid = tid >> 5;
    const int wm = wid & 3;   // 4 warps along M: 4*32 = 128
    const int wn = wid >> 2;  // 2 warps along N: 2*32 = 64
    const int bm = blockIdx.y * BM;
    const int bn = blockIdx.x * BN;

    // ---- cp.async stage loader: rows x 64 fp16 (128B), XOR swizzle ----
    auto load_stage = [&](int k0, int s) {
        const uint32_t st = sb + (uint32_t)s * STAGE_BYTES;
#pragma unroll
        for (int it = 0; it < 4; ++it) {              // A: 128 rows * 8 chunks
            int q = tid + it * NTHREADS;
            int row = q >> 3, kc = q & 7;
            uint32_t so = (uint32_t)(row * 128 + ((kc ^ (row & 7)) << 4));
            size_t ge = (size_t)(bm + row) * K + k0 + kc * 8;
            cp_async_16(st + OFF_A + so, A16 + ge);
        }
#pragma unroll
        for (int it = 0; it < 2; ++it) {              // B: 64 rows * 8 chunks
            int q = tid + it * NTHREADS;
            int row = q >> 3, kc = q & 7;
            uint32_t so = (uint32_t)(row * 128 + ((kc ^ (row & 7)) << 4));
            size_t ge = (size_t)(bn + row) * K + k0 + kc * 8;
            cp_async_16(st + OFF_B0 + so, Whi + ge);
            cp_async_16(st + OFF_B1 + so, Wlo + ge);
        }
    };

    // ---- per-lane ldmatrix address components ----
    int aRow[2], bRow[2];
#pragma unroll
    for (int mi = 0; mi < 2; ++mi) aRow[mi] = wm * 32 + mi * 16 + (lane & 15);
#pragma unroll
    for (int g = 0; g < 2; ++g)
        bRow[g] = wn * 32 + g * 16 + ((lane >> 4) << 3) + (lane & 7);
    const int aCh = lane >> 4;
    const int bCh = (lane >> 3) & 1;

    float acc[2][4][4];
#pragma unroll
    for (int mi = 0; mi < 2; ++mi)
#pragma unroll
        for (int ni = 0; ni < 4; ++ni)
#pragma unroll
            for (int r = 0; r < 4; ++r) acc[mi][ni][r] = 0.f;

    // double-buffered fragments
    uint32_t af[2][2][4], bh[2][2][4], bl[2][2][4];

    auto load_frags = [&](uint32_t st, int k, int b) {
#pragma unroll
        for (int mi = 0; mi < 2; ++mi) {
            uint32_t off = (uint32_t)(aRow[mi] * 128 +
                            (((2 * k + aCh) ^ (aRow[mi] & 7)) << 4));
            ldsm_x4(af[b][mi], st + OFF_A + off);
        }
#pragma unroll
        for (int g = 0; g < 2; ++g) {
            uint32_t off = (uint32_t)(bRow[g] * 128 +
                            (((2 * k + bCh) ^ (bRow[g] & 7)) << 4));
            ldsm_x4(bh[b][g], st + OFF_B0 + off);
            ldsm_x4(bl[b][g], st + OFF_B1 + off);
        }
    };

    auto do_mmas = [&](int b) {
        // pass-major: 8 independent MMAs between accumulator reuses
#pragma unroll
        for (int mi = 0; mi < 2; ++mi)
#pragma unroll
            for (int ni = 0; ni < 4; ++ni)
                mma_fp16(acc[mi][ni], af[b][mi], &bh[b][ni >> 1][(ni & 1) * 2]);
#pragma unroll
        for (int mi = 0; mi < 2; ++mi)
#pragma unroll
            for (int ni = 0; ni < 4; ++ni)
                mma_fp16(acc[mi][ni], af[b][mi], &bl[b][ni >> 1][(ni & 1) * 2]);
    };

    const int NS = K / BK;
    load_stage(0, 0);  CP_COMMIT();
    load_stage(BK, 1); CP_COMMIT();

    for (int i = 0; i < NS; ++i) {
        const int s = i % NSTAGES;
        const uint32_t stc = sb + (uint32_t)s * STAGE_BYTES;
        CP_WAIT(1);            // per-thread: group for stage i complete
        __syncthreads();       // all threads' stage-i data visible; slot (i-1)%3 free
        if (i + 2 < NS) load_stage((i + 2) * BK, (i + 2) % NSTAGES);
        CP_COMMIT();           // always commit (empty groups keep numbering uniform)

        load_frags(stc, 0, 0);
#pragma unroll
        for (int k = 0; k < 4; ++k) {
            if (k < 3) load_frags(stc, k + 1, (k + 1) & 1);
            do_mmas(k & 1);
        }
    }

    // ---- epilogue: scale, bias add, write fp32 + fp16 ----
    const int quad = lane >> 2;
    const int tc = (lane & 3) * 2;
#pragma unroll
    for (int mi = 0; mi < 2; ++mi) {
#pragma unroll
        for (int ni = 0; ni < 4; ++ni) {
            const int col = bn + wn * 32 + ni * 8 + tc;
            const int r0 = bm + wm * 32 + mi * 16 + quad;
            const float2 b2 = *reinterpret_cast<const float2*>(bias + col);
            float2 o0, o1;
            o0.x = acc[mi][ni][0] * WSCALE_INV + b2.x;
            o0.y = acc[mi][ni][1] * WSCALE_INV + b2.y;
            o1.x = acc[mi][ni][2] * WSCALE_INV + b2.x;
            o1.y = acc[mi][ni][3] * WSCALE_INV + b2.y;
            *reinterpret_cast<float2*>(Vout + (size_t)r0 * N + col) = o0;
            *reinterpret_cast<float2*>(Vout + (size_t)(r0 + 8) * N + col) = o1;

            __half2 h0, h1;
            h0.x = __float2half_rn(o0.x); h0.y = __float2half_rn(o0.y);
            h1.x = __float2half_rn(o1.x); h1.y = __float2half_rn(o1.y);
            *reinterpret_cast<__half2*>(OutA16 + (size_t)r0 * N + col) = h0;
            *reinterpret_cast<__half2*>(OutA16 + (size_t)(r0 + 8) * N + col) = h1;
        }
    }
}

// ---------------- fp32 -> scaled fp16 hi/lo split (weights) ----------------
__global__ __launch_bounds__(256)
void split_w_kernel(const float* __restrict__ src,
                    __half* __restrict__ hi,
                    __half* __restrict__ lo,
                    size_t n) {
    size_t i = ((size_t)blockIdx.x * 256 + threadIdx.x) * 4;
    if (i >= n) return;
    float4 x = *reinterpret_cast<const float4*>(src + i);
    x.x *= WSCALE; x.y *= WSCALE; x.z *= WSCALE; x.w *= WSCALE;
    __half2 hh0, hh1, ll0, ll1;
    hh0.x = __float2half_rn(x.x); hh0.y = __float2half_rn(x.y);
    hh1.x = __float2half_rn(x.z); hh1.y = __float2half_rn(x.w);
    ll0.x = __float2half_rn(x.x - __half2float(hh0.x));
    ll0.y = __float2half_rn(x.y - __half2float(hh0.y));
    ll1.x = __float2half_rn(x.z - __half2float(hh1.x));
    ll1.y = __float2half_rn(x.w - __half2float(hh1.y));
    *reinterpret_cast<__half2*>(hi + i) = hh0;
    *reinterpret_cast<__half2*>(hi + i + 2) = hh1;
    *reinterpret_cast<__half2*>(lo + i) = ll0;
    *reinterpret_cast<__half2*>(lo + i + 2) = ll1;
}

// ---------------- fp32 -> fp16 convert (activations) ----------------
__global__ __launch_bounds__(256)
void cvt_fp16_kernel(const float* __restrict__ src,
                     __half* __restrict__ dst, size_t n) {
    size_t i = ((size_t)blockIdx.x * 256 + threadIdx.x) * 4;
    if (i >= n) return;
    float4 x = *reinterpret_cast<const float4*>(src + i);
    __half2 h0, h1;
    h0.x = __float2half_rn(x.x); h0.y = __float2half_rn(x.y);
    h1.x = __float2half_rn(x.z); h1.y = __float2half_rn(x.w);
    *reinterpret_cast<__half2*>(dst + i) = h0;
    *reinterpret_cast<__half2*>(dst + i + 2) = h1;
}

// ---------------- Householder reflection ----------------
__global__ __launch_bounds__(256)
void hflow_kernel(const float* __restrict__ V,
                  const float* __restrict__ Zin,
                  float* __restrict__ Zout, int L) {
    const size_t base = (size_t)blockIdx.x * L;
    const float4* v4 = reinterpret_cast<const float4*>(V + base);
    const float4* z4 = reinterpret_cast<const float4*>(Zin + base);
    float4* o4 = reinterpret_cast<float4*>(Zout + base);
    const int n4 = L >> 2;

    float4 vr[4], zr[4];
    float vz = 0.f, vv = 0.f;
    int cnt = 0;
    for (int idx = threadIdx.x; idx < n4; idx += 256) {
        const float4 v = v4[idx];
        const float4 z = z4[idx];
        vr[cnt] = v; zr[cnt] = z; ++cnt;
        vz += v.x * z.x + v.y * z.y + v.z * z.z + v.w * z.w;
        vv += v.x * v.x + v.y * v.y + v.z * v.z + v.w * v.w;
    }
#pragma unroll
    for (int off = 16; off > 0; off >>= 1) {
        vz += __shfl_xor_sync(0xffffffffu, vz, off);
        vv += __shfl_xor_sync(0xffffffffu, vv, off);
    }
    __shared__ float svz[8], svv[8];
    const int w = threadIdx.x >> 5;
    if ((threadIdx.x & 31) == 0) { svz[w] = vz; svv[w] = vv; }
    __syncthreads();
    float tvz = 0.f, tvv = 0.f;
#pragma unroll
    for (int i = 0; i < 8; ++i) { tvz += svz[i]; tvv += svv[i]; }
    const float s = -2.0f * tvz / tvv;

    cnt = 0;
    for (int idx = threadIdx.x; idx < n4; idx += 256) {
        const float4 v = vr[cnt];
        const float4 z = zr[cnt]; ++cnt;
        o4[idx] = make_float4(z.x + s * v.x, z.y + s * v.y,
                              z.z + s * v.z, z.w + s * v.w);
    }
}

// ---------------- host launcher ----------------
extern "C" void kernel_launch(void* const* d_in, const int* in_sizes, int n_in,
                              void* d_out, int out_size) {
    const float* z      = (const float*)d_in[0];  // [B, L]
    const float* h_last = (const float*)d_in[1];  // [B, H]
    const float* W0     = (const float*)d_in[2];  // [L, H]
    const float* b0     = (const float*)d_in[3];  // [L]
    const float* Ws     = (const float*)d_in[4];  // [NF-1, L, L]
    const float* bs     = (const float*)d_in[5];  // [NF-1, L]

    const int L = in_sizes[3];
    const int B = in_sizes[0] / L;
    const int H = in_sizes[2] / L;
    const int nsteps = in_sizes[5] / L;  // NF - 1

    float* zout = (float*)d_out;

    void *pwh, *pwl, *pa, *pv;
    cudaGetSymbolAddress(&pwh, g_w_hi);
    cudaGetSymbolAddress(&pwl, g_w_lo);
    cudaGetSymbolAddress(&pa, g_a16);
    cudaGetSymbolAddress(&pv, g_v);
    __half* whi = (__half*)pwh;
    __half* wlo = (__half*)pwl;
    __half* a16[2] = {(__half*)pa, (__half*)pa + (size_t)MAXB * MAXL};
    float* v = (float*)pv;

    cudaFuncSetAttribute(mma_fp16x2_kernel,
                         cudaFuncAttributeMaxDynamicSharedMemorySize, SMEM_TOTAL);

    // weight splits (scaled by 50) + first activation convert
    {
        size_t n0 = (size_t)L * H;
        split_w_kernel<<<(unsigned)(n0 / 4 / 256), 256>>>(W0, whi, wlo, n0);
        size_t nw = (size_t)nsteps * L * L;
        split_w_kernel<<<(unsigned)(nw / 4 / 256), 256>>>(Ws, whi + n0, wlo + n0, nw);
        size_t na = (size_t)B * H;
        cvt_fp16_kernel<<<(unsigned)(na / 4 / 256), 256>>>(h_last, a16[0], na);
    }

    const dim3 gblock(NTHREADS);
    const dim3 ggrid(L / BN, B / BM);

    int cur = 0;
    for (int j = 0; j <= nsteps; ++j) {
        const int K = (j == 0) ? H : L;
        const __half* wh = whi + ((j == 0) ? 0 : (size_t)L * H + (size_t)(j - 1) * L * L);
        const __half* wl = wlo + ((j == 0) ? 0 : (size_t)L * H + (size_t)(j - 1) * L * L);
        const float* bias = (j == 0) ? b0 : bs + (size_t)(j - 1) * L;
        const int nxt = cur ^ 1;

        mma_fp16x2_kernel<<<ggrid, gblock, SMEM_TOTAL>>>(
            a16[cur], wh, wl, bias, v, a16[nxt], B, L, K);
        hflow_kernel<<<B, 256>>>(v, (j == 0) ? z : zout, zout, L);
        cur = nxt;
    }
}